// round 10
// baseline (speedup 1.0000x reference)
#include <cuda_runtime.h>
#include <cuda_bf16.h>

// Problem constants (from reference)
#define NUM_IDS   100000
#define FEAT_DIM  512
#define BATCH     512
#define KNEG      100
#define MARGIN    0.03f

#define WARPS_PER_BLOCK 8
#define THREADS_MAIN    (WARPS_PER_BLOCK * 32)   // 256

// Scratch (no cudaMalloc allowed).
// g_label_map encoding: 0 = untouched, b+1 = prototype row overridden by
// teachor_ftr[b]. Zero-initialized at module load; each call resets only the
// (<=512) entries it touches, so no 100K-wide clear is ever needed.
__device__ int          g_label_map[NUM_IDS];
__device__ float        g_partials[BATCH];
__device__ unsigned int g_done_counter;

__device__ __forceinline__ int clampi(int v, int lo, int hi) {
    return v < lo ? lo : (v > hi ? hi : v);
}

// ---------------------------------------------------------------------------
// Kernel A: single block. Phase 1 clears the map entries this call will use
// (same entries every replay since inputs are constant), phase 2 scatters with
// "last write wins" (max b) semantics. Also resets the done-counter.
// ---------------------------------------------------------------------------
__global__ void __launch_bounds__(BATCH)
prep_map_kernel(const int* __restrict__ label) {
    const int b = threadIdx.x;
    const int l = clampi(label[b], 0, NUM_IDS - 1);
    g_label_map[l] = 0;
    if (b == 0) g_done_counter = 0u;
    __syncthreads();
    atomicMax(&g_label_map[l], b + 1);
}

// ---------------------------------------------------------------------------
// Kernel B: one block (8 warps, 256 thr) per batch row b; 100 rows/block.
// loss_{b,k} = relu(g_k . (ftr_b - tftr_b) - MARGIN); u staged in smem.
// vs R9: SOFTWARE PIPELINE — the next row-pair's 8 float4 are prefetched into
// registers before computing the current pair, overlapping gather latency
// with the FMA tree + paired-butterfly reduction. Occupancy is grid-limited
// (3.46 blk/SM), so the extra ~40 data registers are free up to ~85 regs;
// __launch_bounds__(256,3) keeps 3 blocks resident.
// ---------------------------------------------------------------------------
__global__ void __launch_bounds__(THREADS_MAIN, 3)
couple_loss_main(const float* __restrict__ ftr,
                 const float* __restrict__ tftr,
                 const int* __restrict__ label,
                 const float* __restrict__ protos,
                 const int* __restrict__ idH,
                 float* __restrict__ out) {
    const int b    = blockIdx.x;
    const int tid  = threadIdx.x;
    const int warp = tid >> 5;
    const int lane = tid & 31;

    __shared__ float4 sh_u[FEAT_DIM / 4];          // 2 KB: ftr[b]-tftr[b]
    __shared__ const float4* sh_row[KNEG];         // 800 B: resolved row ptrs
    __shared__ float warp_loss[WARPS_PER_BLOCK];
    __shared__ bool  is_last;

    // u = ftr[b] - tftr[b] on threads 0..127; pointer resolution for the 100
    // negatives on threads 128..227 — disjoint threads, one sync.
    if (tid < FEAT_DIM / 4) {
        const float4* f4 = (const float4*)(ftr  + (size_t)b * FEAT_DIM);
        const float4* t4 = (const float4*)(tftr + (size_t)b * FEAT_DIM);
        float4 fv = f4[tid];
        float4 tv = t4[tid];
        sh_u[tid] = make_float4(fv.x - tv.x, fv.y - tv.y,
                                fv.z - tv.z, fv.w - tv.w);
    } else if (tid < FEAT_DIM / 4 + KNEG) {
        const int k    = tid - FEAT_DIM / 4;
        const int lab  = clampi(label[b], 0, NUM_IDS - 1);
        const int neg  = clampi(idH[lab * KNEG + k], 0, NUM_IDS - 1);
        const int bsrc = g_label_map[neg];          // 0 = untouched, else b'+1
        sh_row[k] = (bsrc > 0)
            ? (const float4*)(tftr + (size_t)(bsrc - 1) * FEAT_DIM)
            : (const float4*)(protos + (size_t)neg * FEAT_DIM);
    }
    __syncthreads();

    const bool upper = (lane & 16) != 0;
    float lsum = 0.f;   // lower lanes: relu-sum of row1s; upper: row2s

    // Pair j for warp w: rows (w+16j, w+16j+8). 6 pairs for all warps, plus a
    // degenerate tail pair (w+96, -) for w<4.
    int r = warp;
    {
        const float4* __restrict__ p1 = sh_row[r];
        const float4* __restrict__ p2 = sh_row[r + 8];   // warp+8 < 100 always
        // current pair buffers (preloaded)
        float4 a0 = p1[lane], a1 = p1[lane + 32];
        float4 a2 = p1[lane + 64], a3 = p1[lane + 96];
        float4 c0 = p2[lane], c1 = p2[lane + 32];
        float4 c2 = p2[lane + 64], c3 = p2[lane + 96];

        for (;;) {
            const bool has2 = (r + 8 < KNEG);
            const int  rn   = r + 16;
            const bool more = (rn < KNEG);

            // ---- prefetch next pair into registers (overlaps compute) ----
            float4 n0, n1, n2, n3, m0, m1, m2, m3;
            if (more) {
                const float4* __restrict__ q1 = sh_row[rn];
                const float4* __restrict__ q2 =
                    sh_row[(rn + 8 < KNEG) ? rn + 8 : rn];
                n0 = q1[lane];      n1 = q1[lane + 32];
                n2 = q1[lane + 64]; n3 = q1[lane + 96];
                m0 = q2[lane];      m1 = q2[lane + 32];
                m2 = q2[lane + 64]; m3 = q2[lane + 96];
            }

            // ---- compute current pair (u read from smem) ----
            const float4 u0 = sh_u[lane];
            const float4 u1 = sh_u[lane + 32];
            const float4 u2 = sh_u[lane + 64];
            const float4 u3 = sh_u[lane + 96];

            float4 A, C;
            A.x = a0.x * u0.x; A.y = a0.y * u0.y;
            A.z = a0.z * u0.z; A.w = a0.w * u0.w;
            A.x = fmaf(a1.x, u1.x, A.x); A.y = fmaf(a1.y, u1.y, A.y);
            A.z = fmaf(a1.z, u1.z, A.z); A.w = fmaf(a1.w, u1.w, A.w);
            A.x = fmaf(a2.x, u2.x, A.x); A.y = fmaf(a2.y, u2.y, A.y);
            A.z = fmaf(a2.z, u2.z, A.z); A.w = fmaf(a2.w, u2.w, A.w);
            A.x = fmaf(a3.x, u3.x, A.x); A.y = fmaf(a3.y, u3.y, A.y);
            A.z = fmaf(a3.z, u3.z, A.z); A.w = fmaf(a3.w, u3.w, A.w);

            C.x = c0.x * u0.x; C.y = c0.y * u0.y;
            C.z = c0.z * u0.z; C.w = c0.w * u0.w;
            C.x = fmaf(c1.x, u1.x, C.x); C.y = fmaf(c1.y, u1.y, C.y);
            C.z = fmaf(c1.z, u1.z, C.z); C.w = fmaf(c1.w, u1.w, C.w);
            C.x = fmaf(c2.x, u2.x, C.x); C.y = fmaf(c2.y, u2.y, C.y);
            C.z = fmaf(c2.z, u2.z, C.z); C.w = fmaf(c2.w, u2.w, C.w);
            C.x = fmaf(c3.x, u3.x, C.x); C.y = fmaf(c3.y, u3.y, C.y);
            C.z = fmaf(c3.z, u3.z, C.z); C.w = fmaf(c3.w, u3.w, C.w);

            const float s1 = (A.x + A.y) + (A.z + A.w);
            const float s2 = (C.x + C.y) + (C.z + C.w);

            // Paired reduction: xor-16 routes s1 -> lanes 0-15, s2 -> 16-31,
            // then 4 shared butterfly stages.
            float keep = upper ? s2 : s1;
            float send = upper ? s1 : s2;
            float v = keep + __shfl_xor_sync(0xffffffffu, send, 16);
            v += __shfl_xor_sync(0xffffffffu, v, 8);
            v += __shfl_xor_sync(0xffffffffu, v, 4);
            v += __shfl_xor_sync(0xffffffffu, v, 2);
            v += __shfl_xor_sync(0xffffffffu, v, 1);
            if (!upper || has2)
                lsum += fmaxf(v - MARGIN, 0.f);

            if (!more) break;
            r = rn;
            a0 = n0; a1 = n1; a2 = n2; a3 = n3;
            c0 = m0; c1 = m1; c2 = m2; c3 = m3;
        }
    }

    // Combine the two half-warp relu-sums (identical within each half)
    lsum += __shfl_xor_sync(0xffffffffu, lsum, 16);
    if (lane == 0) warp_loss[warp] = lsum;
    __syncthreads();

    if (tid == 0) {
        float acc = 0.f;
#pragma unroll
        for (int w = 0; w < WARPS_PER_BLOCK; ++w) acc += warp_loss[w];
        g_partials[b] = acc;
        __threadfence();
        unsigned int prev = atomicAdd(&g_done_counter, 1u);
        is_last = (prev == (unsigned int)(BATCH - 1));
    }
    __syncthreads();

    // Last block reduces the 512 partials (L2-resident)
    if (is_last) {
        __threadfence();
        __shared__ float sh[THREADS_MAIN];
        float acc = 0.f;
        for (int i = tid; i < BATCH; i += THREADS_MAIN) acc += g_partials[i];
        sh[tid] = acc;
        __syncthreads();
#pragma unroll
        for (int off = THREADS_MAIN / 2; off > 0; off >>= 1) {
            if (tid < off) sh[tid] += sh[tid + off];
            __syncthreads();
        }
        if (tid == 0)
            out[0] = sh[0] * (1.0f / (float)(BATCH * KNEG));
    }
}

// ---------------------------------------------------------------------------
extern "C" void kernel_launch(void* const* d_in, const int* in_sizes, int n_in,
                              void* d_out, int out_size) {
    const float* ftr    = (const float*)d_in[0];
    const float* tftr   = (const float*)d_in[1];
    const int*   label  = (const int*)d_in[2];
    const float* protos = (const float*)d_in[3];
    const int*   idH    = (const int*)d_in[4];
    float* out = (float*)d_out;

    prep_map_kernel<<<1, BATCH>>>(label);
    couple_loss_main<<<BATCH, THREADS_MAIN>>>(ftr, tftr, label, protos,
                                              idH, out);
}

// round 11
// speedup vs baseline: 1.3855x; 1.3855x over previous
#include <cuda_runtime.h>
#include <cuda_bf16.h>

// Problem constants (from reference)
#define NUM_IDS   100000
#define FEAT_DIM  512
#define BATCH     512
#define KNEG      100
#define MARGIN    0.03f

#define WARPS_PER_BLOCK 8
#define THREADS_MAIN    (WARPS_PER_BLOCK * 32)   // 256

// Scratch (no cudaMalloc allowed).
// g_label_map encoding: 0 = untouched, b+1 = prototype row overridden by
// teachor_ftr[b]. Zero-initialized at module load; each call resets only the
// (<=512) entries it touches, so no 100K-wide clear is ever needed.
__device__ int          g_label_map[NUM_IDS];
__device__ float        g_partials[BATCH];
__device__ unsigned int g_done_counter;

__device__ __forceinline__ int clampi(int v, int lo, int hi) {
    return v < lo ? lo : (v > hi ? hi : v);
}

// ---------------------------------------------------------------------------
// Kernel A: single block. Phase 1 clears the map entries this call will use
// (same entries every replay since inputs are constant), phase 2 scatters with
// "last write wins" (max b) semantics. Also resets the done-counter.
// ---------------------------------------------------------------------------
__global__ void __launch_bounds__(BATCH)
prep_map_kernel(const int* __restrict__ label) {
    const int b = threadIdx.x;
    const int l = clampi(label[b], 0, NUM_IDS - 1);
    g_label_map[l] = 0;
    if (b == 0) g_done_counter = 0u;
    __syncthreads();
    atomicMax(&g_label_map[l], b + 1);
}

// ---------------------------------------------------------------------------
// Kernel B: one block (8 warps, 256 thr) per batch row b; 100 rows/block.
// loss_{b,k} = relu(g_k . (ftr_b - tftr_b) - MARGIN); u in 16 regs per lane.
// vs R9 (best): the in-loop 5-shfl reduction chain is DEFERRED — each lane
// stores its scalar per-row partial to padded smem (1 conflict-free STS per
// row), and a post-sweep pass sums 32 lane-partials per row, applies relu,
// and block-reduces. Hot loop = pure LDG.128 -> FMA tree -> STS, no cross-
// lane dependency on the critical path, regs stay ~46 (occupancy preserved).
// ---------------------------------------------------------------------------
#define PPITCH 33   // 32 lanes + 1 pad -> conflict-free rows and columns

__global__ void __launch_bounds__(THREADS_MAIN)
couple_loss_main(const float* __restrict__ ftr,
                 const float* __restrict__ tftr,
                 const int* __restrict__ label,
                 const float* __restrict__ protos,
                 const int* __restrict__ idH,
                 float* __restrict__ out) {
    const int b    = blockIdx.x;
    const int tid  = threadIdx.x;
    const int warp = tid >> 5;
    const int lane = tid & 31;

    __shared__ float4 sh_u[FEAT_DIM / 4];           // 2 KB: ftr[b]-tftr[b]
    __shared__ const float4* sh_row[KNEG];          // 800 B: resolved ptrs
    __shared__ float sh_part[KNEG * PPITCH];        // 12.9 KB lane partials
    __shared__ float sh_red[128];
    __shared__ bool  is_last;

    // u = ftr[b] - tftr[b] on threads 0..127; pointer resolution for the 100
    // negatives on threads 128..227 — disjoint threads, one sync.
    if (tid < FEAT_DIM / 4) {
        const float4* f4 = (const float4*)(ftr  + (size_t)b * FEAT_DIM);
        const float4* t4 = (const float4*)(tftr + (size_t)b * FEAT_DIM);
        float4 fv = f4[tid];
        float4 tv = t4[tid];
        sh_u[tid] = make_float4(fv.x - tv.x, fv.y - tv.y,
                                fv.z - tv.z, fv.w - tv.w);
    } else if (tid < FEAT_DIM / 4 + KNEG) {
        const int k    = tid - FEAT_DIM / 4;
        const int lab  = clampi(label[b], 0, NUM_IDS - 1);
        const int neg  = clampi(idH[lab * KNEG + k], 0, NUM_IDS - 1);
        const int bsrc = g_label_map[neg];          // 0 = untouched, else b'+1
        sh_row[k] = (bsrc > 0)
            ? (const float4*)(tftr + (size_t)(bsrc - 1) * FEAT_DIM)
            : (const float4*)(protos + (size_t)neg * FEAT_DIM);
    }
    __syncthreads();

    // Keep u in registers for the whole sweep (4 float4 per lane)
    const float4 u0 = sh_u[lane];
    const float4 u1 = sh_u[lane + 32];
    const float4 u2 = sh_u[lane + 64];
    const float4 u3 = sh_u[lane + 96];

    // Warp w handles rows w, w+8, ... ; two rows in flight per iteration.
    // Per row, each lane stores its scalar partial; no in-loop reduction.
    for (int r = warp; r < KNEG; r += 2 * WARPS_PER_BLOCK) {
        const int  r2   = r + WARPS_PER_BLOCK;
        const bool has2 = (r2 < KNEG);
        const float4* __restrict__ p1 = sh_row[r];
        const float4* __restrict__ p2 = sh_row[has2 ? r2 : r];

        float4 a0 = p1[lane];
        float4 a1 = p1[lane + 32];
        float4 a2 = p1[lane + 64];
        float4 a3 = p1[lane + 96];
        float4 c0 = p2[lane];
        float4 c1 = p2[lane + 32];
        float4 c2 = p2[lane + 64];
        float4 c3 = p2[lane + 96];

        // 4 independent accumulator chains per row (depth 8 each)
        float4 A, C;
        A.x = a0.x * u0.x; A.y = a0.y * u0.y;
        A.z = a0.z * u0.z; A.w = a0.w * u0.w;
        A.x = fmaf(a1.x, u1.x, A.x); A.y = fmaf(a1.y, u1.y, A.y);
        A.z = fmaf(a1.z, u1.z, A.z); A.w = fmaf(a1.w, u1.w, A.w);
        A.x = fmaf(a2.x, u2.x, A.x); A.y = fmaf(a2.y, u2.y, A.y);
        A.z = fmaf(a2.z, u2.z, A.z); A.w = fmaf(a2.w, u2.w, A.w);
        A.x = fmaf(a3.x, u3.x, A.x); A.y = fmaf(a3.y, u3.y, A.y);
        A.z = fmaf(a3.z, u3.z, A.z); A.w = fmaf(a3.w, u3.w, A.w);

        C.x = c0.x * u0.x; C.y = c0.y * u0.y;
        C.z = c0.z * u0.z; C.w = c0.w * u0.w;
        C.x = fmaf(c1.x, u1.x, C.x); C.y = fmaf(c1.y, u1.y, C.y);
        C.z = fmaf(c1.z, u1.z, C.z); C.w = fmaf(c1.w, u1.w, C.w);
        C.x = fmaf(c2.x, u2.x, C.x); C.y = fmaf(c2.y, u2.y, C.y);
        C.z = fmaf(c2.z, u2.z, C.z); C.w = fmaf(c2.w, u2.w, C.w);
        C.x = fmaf(c3.x, u3.x, C.x); C.y = fmaf(c3.y, u3.y, C.y);
        C.z = fmaf(c3.z, u3.z, C.z); C.w = fmaf(c3.w, u3.w, C.w);

        // Store per-lane partials (conflict-free: bank = (r + lane) % 32)
        sh_part[r * PPITCH + lane] = (A.x + A.y) + (A.z + A.w);
        if (has2)
            sh_part[r2 * PPITCH + lane] = (C.x + C.y) + (C.z + C.w);
    }
    __syncthreads();

    // Deferred reduction: thread t (<100) sums row t's 32 lane-partials
    // (conflict-free via PPITCH padding), applies relu-margin.
    float v = 0.f;
    if (tid < KNEG) {
        const float* rowp = &sh_part[tid * PPITCH];
        float acc0 = 0.f, acc1 = 0.f, acc2 = 0.f, acc3 = 0.f;
#pragma unroll
        for (int j = 0; j < 32; j += 4) {
            acc0 += rowp[j];     acc1 += rowp[j + 1];
            acc2 += rowp[j + 2]; acc3 += rowp[j + 3];
        }
        v = fmaxf((acc0 + acc1) + (acc2 + acc3) - MARGIN, 0.f);
    }
    if (tid < 128) sh_red[tid] = 0.f;
    __syncthreads();
    if (tid < KNEG) sh_red[tid] = v;
    __syncthreads();
    if (tid < 64) sh_red[tid] += sh_red[tid + 64];
    __syncthreads();
    if (tid < 32) {
        float s = sh_red[tid] + sh_red[tid + 32];
#pragma unroll
        for (int off = 16; off > 0; off >>= 1)
            s += __shfl_xor_sync(0xffffffffu, s, off);
        if (tid == 0) {
            g_partials[b] = s;
            __threadfence();
            unsigned int prev = atomicAdd(&g_done_counter, 1u);
            is_last = (prev == (unsigned int)(BATCH - 1));
        }
    }
    __syncthreads();

    // Last block reduces the 512 partials (L2-resident)
    if (is_last) {
        __threadfence();
        float acc = 0.f;
        for (int i = tid; i < BATCH; i += THREADS_MAIN) acc += g_partials[i];
        __syncthreads();            // sh_red reuse safe
        sh_red[tid >> 1] = 0.f;     // not needed; keep simple below
        __syncthreads();
        // block reduce 256 values deterministically via smem tree
        __shared__ float sh2[THREADS_MAIN];
        sh2[tid] = acc;
        __syncthreads();
#pragma unroll
        for (int off = THREADS_MAIN / 2; off > 0; off >>= 1) {
            if (tid < off) sh2[tid] += sh2[tid + off];
            __syncthreads();
        }
        if (tid == 0)
            out[0] = sh2[0] * (1.0f / (float)(BATCH * KNEG));
    }
}

// ---------------------------------------------------------------------------
extern "C" void kernel_launch(void* const* d_in, const int* in_sizes, int n_in,
                              void* d_out, int out_size) {
    const float* ftr    = (const float*)d_in[0];
    const float* tftr   = (const float*)d_in[1];
    const int*   label  = (const int*)d_in[2];
    const float* protos = (const float*)d_in[3];
    const int*   idH    = (const int*)d_in[4];
    float* out = (float*)d_out;

    prep_map_kernel<<<1, BATCH>>>(label);
    couple_loss_main<<<BATCH, THREADS_MAIN>>>(ftr, tftr, label, protos,
                                              idH, out);
}

// round 13
// speedup vs baseline: 1.3976x; 1.0087x over previous
#include <cuda_runtime.h>
#include <cuda_bf16.h>

// Problem constants (from reference)
#define NUM_IDS   100000
#define FEAT_DIM  512
#define BATCH     512
#define KNEG      100
#define MARGIN    0.03f

#define WARPS_PER_BLOCK 8
#define THREADS_MAIN    (WARPS_PER_BLOCK * 32)   // 256

#define HASH_SIZE 2048                            // 512 labels @ 25% load
#define HASH_MASK (HASH_SIZE - 1)
#define PPITCH    33    // 32 lanes + 1 pad -> conflict-free partials

// Scratch (no cudaMalloc allowed). g_done_counter is self-resetting: the
// last block of each launch zeroes it, so every graph replay starts at 0.
__device__ float        g_partials[BATCH];
__device__ unsigned int g_done_counter;   // zero-initialized at module load

__device__ __forceinline__ int clampi(int v, int lo, int hi) {
    return v < lo ? lo : (v > hi ? hi : v);
}

__device__ __forceinline__ unsigned int hash_id(int l) {
    return (((unsigned int)l * 2654435761u) >> 21) & HASH_MASK;
}

// ---------------------------------------------------------------------------
// Single kernel: one block (8 warps, 256 thr) per batch row b.
//
// Scatter semantics (protos.at[label].set(teachor_ftr), last write wins) are
// resolved per block via a smem hash of the 512 labels -> max batch index.
// This removes the separate prep kernel and its ~2-3us graph-serialized
// launch boundary; the hash build is a few hundred cycles, parallel in all
// 512 blocks, against L2-hot label data. The hash's final contents are
// insertion-order independent (CAS slot claim + commutative atomicMax), so
// the output is replay-deterministic.
//
// loss_{b,k} = relu(g_k . (ftr_b - tftr_b) - MARGIN); u in 16 regs per lane.
// Hot loop: pure LDG.128 -> 4-chain FMA tree -> 1 STS (deferred reduction);
// post-sweep pass sums 32 lane-partials per row, relu, block-reduce; last
// finished block reduces the 512 partials (L2-hot) and writes the mean.
// ---------------------------------------------------------------------------
__global__ void __launch_bounds__(THREADS_MAIN)
couple_loss_main(const float* __restrict__ ftr,
                 const float* __restrict__ tftr,
                 const int* __restrict__ label,
                 const float* __restrict__ protos,
                 const int* __restrict__ idH,
                 float* __restrict__ out) {
    const int b    = blockIdx.x;
    const int tid  = threadIdx.x;
    const int warp = tid >> 5;
    const int lane = tid & 31;

    __shared__ float4 sh_u[FEAT_DIM / 4];           // 2 KB: ftr[b]-tftr[b]
    __shared__ const float4* sh_row[KNEG];          // 800 B resolved ptrs
    __shared__ float sh_part[KNEG * PPITCH];        // 12.9 KB lane partials
    __shared__ int   hkey[HASH_SIZE];               // 8 KB
    __shared__ int   hval[HASH_SIZE];               // 8 KB (0=none, b+1)
    __shared__ float sh_red[128];
    __shared__ bool  is_last;

    // ---- Phase 1: hash init (all threads) + u build (threads 0..127) ----
#pragma unroll
    for (int j = 0; j < HASH_SIZE / THREADS_MAIN; ++j) {
        hkey[tid + j * THREADS_MAIN] = -1;
        hval[tid + j * THREADS_MAIN] = 0;
    }
    if (tid < FEAT_DIM / 4) {
        const float4* f4 = (const float4*)(ftr  + (size_t)b * FEAT_DIM);
        const float4* t4 = (const float4*)(tftr + (size_t)b * FEAT_DIM);
        float4 fv = f4[tid];
        float4 tv = t4[tid];
        sh_u[tid] = make_float4(fv.x - tv.x, fv.y - tv.y,
                                fv.z - tv.z, fv.w - tv.w);
    }
    __syncthreads();

    // ---- Phase 2: insert the 512 labels (last-write-wins via max b) ----
#pragma unroll
    for (int j = 0; j < BATCH / THREADS_MAIN; ++j) {
        const int i = tid + j * THREADS_MAIN;
        const int l = clampi(label[i], 0, NUM_IDS - 1);
        unsigned int idx = hash_id(l);
        for (;;) {
            const int prev = atomicCAS(&hkey[idx], -1, l);
            if (prev == -1 || prev == l) {
                atomicMax(&hval[idx], i + 1);
                break;
            }
            idx = (idx + 1) & HASH_MASK;
        }
    }
    __syncthreads();

    // ---- Phase 3: resolve the 100 gather-row pointers ----
    if (tid < KNEG) {
        const int lab = clampi(label[b], 0, NUM_IDS - 1);
        const int neg = clampi(idH[lab * KNEG + tid], 0, NUM_IDS - 1);
        int bsrc = 0;
        unsigned int idx = hash_id(neg);
        for (;;) {
            const int k = hkey[idx];
            if (k == -1) break;               // not overridden
            if (k == neg) { bsrc = hval[idx]; break; }
            idx = (idx + 1) & HASH_MASK;
        }
        sh_row[tid] = (bsrc > 0)
            ? (const float4*)(tftr + (size_t)(bsrc - 1) * FEAT_DIM)
            : (const float4*)(protos + (size_t)neg * FEAT_DIM);
    }
    __syncthreads();

    // Keep u in registers for the whole sweep (4 float4 per lane)
    const float4 u0 = sh_u[lane];
    const float4 u1 = sh_u[lane + 32];
    const float4 u2 = sh_u[lane + 64];
    const float4 u3 = sh_u[lane + 96];

    // ---- Sweep: warp w handles rows w, w+8, ...; two rows in flight. ----
    for (int r = warp; r < KNEG; r += 2 * WARPS_PER_BLOCK) {
        const int  r2   = r + WARPS_PER_BLOCK;
        const bool has2 = (r2 < KNEG);
        const float4* __restrict__ p1 = sh_row[r];
        const float4* __restrict__ p2 = sh_row[has2 ? r2 : r];

        float4 a0 = p1[lane];
        float4 a1 = p1[lane + 32];
        float4 a2 = p1[lane + 64];
        float4 a3 = p1[lane + 96];
        float4 c0 = p2[lane];
        float4 c1 = p2[lane + 32];
        float4 c2 = p2[lane + 64];
        float4 c3 = p2[lane + 96];

        // 4 independent accumulator chains per row (depth 8 each)
        float4 A, C;
        A.x = a0.x * u0.x; A.y = a0.y * u0.y;
        A.z = a0.z * u0.z; A.w = a0.w * u0.w;
        A.x = fmaf(a1.x, u1.x, A.x); A.y = fmaf(a1.y, u1.y, A.y);
        A.z = fmaf(a1.z, u1.z, A.z); A.w = fmaf(a1.w, u1.w, A.w);
        A.x = fmaf(a2.x, u2.x, A.x); A.y = fmaf(a2.y, u2.y, A.y);
        A.z = fmaf(a2.z, u2.z, A.z); A.w = fmaf(a2.w, u2.w, A.w);
        A.x = fmaf(a3.x, u3.x, A.x); A.y = fmaf(a3.y, u3.y, A.y);
        A.z = fmaf(a3.z, u3.z, A.z); A.w = fmaf(a3.w, u3.w, A.w);

        C.x = c0.x * u0.x; C.y = c0.y * u0.y;
        C.z = c0.z * u0.z; C.w = c0.w * u0.w;
        C.x = fmaf(c1.x, u1.x, C.x); C.y = fmaf(c1.y, u1.y, C.y);
        C.z = fmaf(c1.z, u1.z, C.z); C.w = fmaf(c1.w, u1.w, C.w);
        C.x = fmaf(c2.x, u2.x, C.x); C.y = fmaf(c2.y, u2.y, C.y);
        C.z = fmaf(c2.z, u2.z, C.z); C.w = fmaf(c2.w, u2.w, C.w);
        C.x = fmaf(c3.x, u3.x, C.x); C.y = fmaf(c3.y, u3.y, C.y);
        C.z = fmaf(c3.z, u3.z, C.z); C.w = fmaf(c3.w, u3.w, C.w);

        // Store per-lane partials (conflict-free: bank = (r + lane) % 32)
        sh_part[r * PPITCH + lane] = (A.x + A.y) + (A.z + A.w);
        if (has2)
            sh_part[r2 * PPITCH + lane] = (C.x + C.y) + (C.z + C.w);
    }
    __syncthreads();

    // ---- Deferred reduction: thread t (<100) sums row t's 32 partials ----
    float v = 0.f;
    if (tid < KNEG) {
        const float* rowp = &sh_part[tid * PPITCH];
        float acc0 = 0.f, acc1 = 0.f, acc2 = 0.f, acc3 = 0.f;
#pragma unroll
        for (int j = 0; j < 32; j += 4) {
            acc0 += rowp[j];     acc1 += rowp[j + 1];
            acc2 += rowp[j + 2]; acc3 += rowp[j + 3];
        }
        v = fmaxf((acc0 + acc1) + (acc2 + acc3) - MARGIN, 0.f);
    }
    if (tid < 128) sh_red[tid] = 0.f;
    __syncthreads();
    if (tid < KNEG) sh_red[tid] = v;
    __syncthreads();
    if (tid < 64) sh_red[tid] += sh_red[tid + 64];
    __syncthreads();
    if (tid < 32) {
        float s = sh_red[tid] + sh_red[tid + 32];
#pragma unroll
        for (int off = 16; off > 0; off >>= 1)
            s += __shfl_xor_sync(0xffffffffu, s, off);
        if (tid == 0) {
            g_partials[b] = s;
            __threadfence();
            unsigned int prev = atomicAdd(&g_done_counter, 1u);
            is_last = (prev == (unsigned int)(BATCH - 1));
        }
    }
    __syncthreads();

    // ---- Last block: reduce the 512 partials, reset counter for replay ----
    if (is_last) {
        if (tid == 0) g_done_counter = 0u;   // all blocks already arrived
        __threadfence();
        __shared__ float sh2[THREADS_MAIN];
        float acc = 0.f;
        for (int i = tid; i < BATCH; i += THREADS_MAIN) acc += g_partials[i];
        sh2[tid] = acc;
        __syncthreads();
#pragma unroll
        for (int off = THREADS_MAIN / 2; off > 0; off >>= 1) {
            if (tid < off) sh2[tid] += sh2[tid + off];
            __syncthreads();
        }
        if (tid == 0)
            out[0] = sh2[0] * (1.0f / (float)(BATCH * KNEG));
    }
}

// ---------------------------------------------------------------------------
extern "C" void kernel_launch(void* const* d_in, const int* in_sizes, int n_in,
                              void* d_out, int out_size) {
    const float* ftr    = (const float*)d_in[0];
    const float* tftr   = (const float*)d_in[1];
    const int*   label  = (const int*)d_in[2];
    const float* protos = (const float*)d_in[3];
    const int*   idH    = (const int*)d_in[4];
    float* out = (float*)d_out;

    couple_loss_main<<<BATCH, THREADS_MAIN>>>(ftr, tftr, label, protos,
                                              idH, out);
}

// round 14
// speedup vs baseline: 1.5189x; 1.0868x over previous
#include <cuda_runtime.h>
#include <cuda_bf16.h>

// Problem constants (from reference)
#define NUM_IDS   100000
#define FEAT_DIM  512
#define BATCH     512
#define KNEG      100
#define MARGIN    0.03f

#define WARPS_PER_BLOCK 8
#define THREADS_MAIN    (WARPS_PER_BLOCK * 32)   // 256

#define HASH_SIZE 2048                            // 512 labels @ 25% load
#define HASH_MASK (HASH_SIZE - 1)
#define PPITCH    33    // 32 lanes + 1 pad -> conflict-free partials

// Scratch (no cudaMalloc allowed). g_done_counter is self-resetting: the
// last block of each launch zeroes it, so every graph replay starts at 0.
__device__ float        g_partials[BATCH];
__device__ unsigned int g_done_counter;   // zero-initialized at module load

__device__ __forceinline__ int clampi(int v, int lo, int hi) {
    return v < lo ? lo : (v > hi ? hi : v);
}

__device__ __forceinline__ unsigned int hash_id(int l) {
    return (((unsigned int)l * 2654435761u) >> 21) & HASH_MASK;
}

// L2-only load of a float4 (no L1 allocation — gathered rows have no L1 reuse)
__device__ __forceinline__ float4 ldcg4(const float4* p) {
    return __ldcg(p);
}

// Dot-product contribution of one 512B chunk-set against u (registers)
#define DOT_ROW(ACC, P)                                                     \
    do {                                                                    \
        float4 v0 = ldcg4((P) + lane);                                      \
        float4 v1 = ldcg4((P) + lane + 32);                                 \
        float4 v2 = ldcg4((P) + lane + 64);                                 \
        float4 v3 = ldcg4((P) + lane + 96);                                 \
        float4 T;                                                           \
        T.x = v0.x * u0.x; T.y = v0.y * u0.y;                               \
        T.z = v0.z * u0.z; T.w = v0.w * u0.w;                               \
        T.x = fmaf(v1.x, u1.x, T.x); T.y = fmaf(v1.y, u1.y, T.y);           \
        T.z = fmaf(v1.z, u1.z, T.z); T.w = fmaf(v1.w, u1.w, T.w);           \
        T.x = fmaf(v2.x, u2.x, T.x); T.y = fmaf(v2.y, u2.y, T.y);           \
        T.z = fmaf(v2.z, u2.z, T.z); T.w = fmaf(v2.w, u2.w, T.w);           \
        T.x = fmaf(v3.x, u3.x, T.x); T.y = fmaf(v3.y, u3.y, T.y);           \
        T.z = fmaf(v3.z, u3.z, T.z); T.w = fmaf(v3.w, u3.w, T.w);           \
        ACC = (T.x + T.y) + (T.z + T.w);                                    \
    } while (0)

// ---------------------------------------------------------------------------
// Single kernel: one block (8 warps, 256 thr) per batch row b.
// Scatter semantics resolved per block via a smem hash (order-independent
// final contents -> replay-deterministic). loss = relu(g . (f - t) - MARGIN).
// Hot loop: 3 rows per warp iteration (12 LDG.128 in flight), L2-only loads,
// deferred reduction via padded smem partials. __launch_bounds__(256,4) pins
// regs <= 64 = the grid-limit boundary (3.46 blk/SM), so extra MLP is free.
// ---------------------------------------------------------------------------
__global__ void __launch_bounds__(THREADS_MAIN, 4)
couple_loss_main(const float* __restrict__ ftr,
                 const float* __restrict__ tftr,
                 const int* __restrict__ label,
                 const float* __restrict__ protos,
                 const int* __restrict__ idH,
                 float* __restrict__ out) {
    const int b    = blockIdx.x;
    const int tid  = threadIdx.x;
    const int warp = tid >> 5;
    const int lane = tid & 31;

    __shared__ float4 sh_u[FEAT_DIM / 4];           // 2 KB: ftr[b]-tftr[b]
    __shared__ const float4* sh_row[KNEG];          // 800 B resolved ptrs
    __shared__ float sh_part[KNEG * PPITCH];        // 12.9 KB lane partials
    __shared__ int   hkey[HASH_SIZE];               // 8 KB
    __shared__ int   hval[HASH_SIZE];               // 8 KB (0=none, b+1)
    __shared__ float sh_red[128];
    __shared__ bool  is_last;

    // ---- Phase 1: hash init (all threads) + u build (threads 0..127) ----
#pragma unroll
    for (int j = 0; j < HASH_SIZE / THREADS_MAIN; ++j) {
        hkey[tid + j * THREADS_MAIN] = -1;
        hval[tid + j * THREADS_MAIN] = 0;
    }
    if (tid < FEAT_DIM / 4) {
        const float4* f4 = (const float4*)(ftr  + (size_t)b * FEAT_DIM);
        const float4* t4 = (const float4*)(tftr + (size_t)b * FEAT_DIM);
        float4 fv = f4[tid];
        float4 tv = t4[tid];
        sh_u[tid] = make_float4(fv.x - tv.x, fv.y - tv.y,
                                fv.z - tv.z, fv.w - tv.w);
    }
    __syncthreads();

    // ---- Phase 2: insert the 512 labels (last-write-wins via max b) ----
#pragma unroll
    for (int j = 0; j < BATCH / THREADS_MAIN; ++j) {
        const int i = tid + j * THREADS_MAIN;
        const int l = clampi(label[i], 0, NUM_IDS - 1);
        unsigned int idx = hash_id(l);
        for (;;) {
            const int prev = atomicCAS(&hkey[idx], -1, l);
            if (prev == -1 || prev == l) {
                atomicMax(&hval[idx], i + 1);
                break;
            }
            idx = (idx + 1) & HASH_MASK;
        }
    }
    __syncthreads();

    // ---- Phase 3: resolve the 100 gather-row pointers ----
    if (tid < KNEG) {
        const int lab = clampi(label[b], 0, NUM_IDS - 1);
        const int neg = clampi(idH[lab * KNEG + tid], 0, NUM_IDS - 1);
        int bsrc = 0;
        unsigned int idx = hash_id(neg);
        for (;;) {
            const int k = hkey[idx];
            if (k == -1) break;               // not overridden
            if (k == neg) { bsrc = hval[idx]; break; }
            idx = (idx + 1) & HASH_MASK;
        }
        sh_row[tid] = (bsrc > 0)
            ? (const float4*)(tftr + (size_t)(bsrc - 1) * FEAT_DIM)
            : (const float4*)(protos + (size_t)neg * FEAT_DIM);
    }
    __syncthreads();

    // Keep u in registers for the whole sweep (4 float4 per lane)
    const float4 u0 = sh_u[lane];
    const float4 u1 = sh_u[lane + 32];
    const float4 u2 = sh_u[lane + 64];
    const float4 u3 = sh_u[lane + 96];

    // ---- Sweep: warp w handles rows == w (mod 8); THREE rows per iter ----
    // Triples at base r = w + 24j cover rows w..w+88; tail row w+96 for w<4.
    for (int r = warp; r + 16 < KNEG; r += 3 * WARPS_PER_BLOCK) {
        const float4* __restrict__ p1 = sh_row[r];
        const float4* __restrict__ p2 = sh_row[r + 8];
        const float4* __restrict__ p3 = sh_row[r + 16];
        float s1, s2, s3;
        DOT_ROW(s1, p1);
        DOT_ROW(s2, p2);
        DOT_ROW(s3, p3);
        sh_part[(r)      * PPITCH + lane] = s1;
        sh_part[(r + 8)  * PPITCH + lane] = s2;
        sh_part[(r + 16) * PPITCH + lane] = s3;
    }
    if (warp + 96 < KNEG) {                     // tail rows 96..99, warps 0-3
        const float4* __restrict__ p1 = sh_row[warp + 96];
        float s1;
        DOT_ROW(s1, p1);
        sh_part[(warp + 96) * PPITCH + lane] = s1;
    }
    __syncthreads();

    // ---- Deferred reduction: thread t (<100) sums row t's 32 partials ----
    float v = 0.f;
    if (tid < KNEG) {
        const float* rowp = &sh_part[tid * PPITCH];
        float acc0 = 0.f, acc1 = 0.f, acc2 = 0.f, acc3 = 0.f;
#pragma unroll
        for (int j = 0; j < 32; j += 4) {
            acc0 += rowp[j];     acc1 += rowp[j + 1];
            acc2 += rowp[j + 2]; acc3 += rowp[j + 3];
        }
        v = fmaxf((acc0 + acc1) + (acc2 + acc3) - MARGIN, 0.f);
    }
    if (tid < 128) sh_red[tid] = 0.f;
    __syncthreads();
    if (tid < KNEG) sh_red[tid] = v;
    __syncthreads();
    if (tid < 64) sh_red[tid] += sh_red[tid + 64];
    __syncthreads();
    if (tid < 32) {
        float s = sh_red[tid] + sh_red[tid + 32];
#pragma unroll
        for (int off = 16; off > 0; off >>= 1)
            s += __shfl_xor_sync(0xffffffffu, s, off);
        if (tid == 0) {
            g_partials[b] = s;
            __threadfence();
            unsigned int prev = atomicAdd(&g_done_counter, 1u);
            is_last = (prev == (unsigned int)(BATCH - 1));
        }
    }
    __syncthreads();

    // ---- Last block: reduce the 512 partials, reset counter for replay ----
    if (is_last) {
        if (tid == 0) g_done_counter = 0u;   // all blocks already arrived
        __threadfence();
        __shared__ float sh2[THREADS_MAIN];
        float acc = 0.f;
        for (int i = tid; i < BATCH; i += THREADS_MAIN) acc += g_partials[i];
        sh2[tid] = acc;
        __syncthreads();
#pragma unroll
        for (int off = THREADS_MAIN / 2; off > 0; off >>= 1) {
            if (tid < off) sh2[tid] += sh2[tid + off];
            __syncthreads();
        }
        if (tid == 0)
            out[0] = sh2[0] * (1.0f / (float)(BATCH * KNEG));
    }
}

// ---------------------------------------------------------------------------
extern "C" void kernel_launch(void* const* d_in, const int* in_sizes, int n_in,
                              void* d_out, int out_size) {
    const float* ftr    = (const float*)d_in[0];
    const float* tftr   = (const float*)d_in[1];
    const int*   label  = (const int*)d_in[2];
    const float* protos = (const float*)d_in[3];
    const int*   idH    = (const int*)d_in[4];
    float* out = (float*)d_out;

    couple_loss_main<<<BATCH, THREADS_MAIN>>>(ftr, tftr, label, protos,
                                              idH, out);
}